// round 2
// baseline (speedup 1.0000x reference)
#include <cuda_runtime.h>
#include <cstdint>

#define BATCH 512
#define NCTX  1000
#define DCTX  128
#define NH    8
#define HID   128
#define TN    128
#define NTILES 8
#define TPB   1024
#define ROWP  132

// ---- smem layout (float offsets) ----
#define OFF_CTX0   0
#define OFF_CTX1   16896
#define OFF_QKT    33792   // 1056: qkT[d][h] swizzled: d*8 + (d>>4)*4 + h
#define OFF_E      34848   // 8*132
#define OFF_WMAX   35904   // 256
#define OFF_WLS    36160   // 256
#define OFF_C      36416   // 1024
#define OFF_X      37440
#define OFF_XF     37568
#define OFF_Z      37696
#define OFF_STATE  37824   // 384
#define OFF_Q      38208   // 128
#define OFF_U      38336   // 1024
#define OFF_MASK   39360   // 256 ints
#define OFF_RED    39616   // 64
#define SMEM_FLOATS 39680
#define SMEM_BYTES  (SMEM_FLOATS * 4)

#define R_MRUN  0
#define R_MNEW  8
#define R_SCALE 16
#define R_LRUN  24
#define R_WARP  32
#define R_UMAX  48
#define R_USUM  49

typedef unsigned long long ull;

__device__ __forceinline__ ull f2pack(float lo, float hi) {
    ull r; asm("mov.b64 %0, {%1,%2};" : "=l"(r) : "f"(lo), "f"(hi)); return r;
}
__device__ __forceinline__ void f2unpack(ull v, float &lo, float &hi) {
    asm("mov.b64 {%0,%1}, %2;" : "=f"(lo), "=f"(hi) : "l"(v));
}
__device__ __forceinline__ ull ffma2(ull a, ull b, ull c) {
    ull d; asm("fma.rn.f32x2 %0, %1, %2, %3;" : "=l"(d) : "l"(a), "l"(b), "l"(c)); return d;
}
__device__ __forceinline__ ull fmul2(ull a, ull b) {
    ull d; asm("mul.rn.f32x2 %0, %1, %2;" : "=l"(d) : "l"(a), "l"(b)); return d;
}

__device__ __forceinline__ void cpasync16(uint32_t dst, const void* src, int srcbytes) {
    asm volatile("cp.async.cg.shared.global [%0], [%1], 16, %2;"
                 :: "r"(dst), "l"(src), "r"(srcbytes));
}
__device__ __forceinline__ void cp_commit() { asm volatile("cp.async.commit_group;"); }
template <int NG> __device__ __forceinline__ void cp_wait() {
    asm volatile("cp.async.wait_group %0;" :: "n"(NG));
}

__device__ __forceinline__ void issue_tile(int tile, int b, const float* __restrict__ context,
                                           const int* __restrict__ mask,
                                           float* S, int t) {
    const int bufi = tile & 1;
    float* dctx = S + (bufi ? OFF_CTX1 : OFF_CTX0);
    int*   dmask = (int*)(S + OFF_MASK) + bufi * 128;
    const int n0 = tile * TN;
#pragma unroll
    for (int k = 0; k < 4; ++k) {
        int idx = t + k * TPB;
        int row = idx >> 5, c4 = idx & 31;
        const float* src = context + ((size_t)b * NCTX + (size_t)(n0 + row)) * DCTX + c4 * 4;
        uint32_t dst = (uint32_t)__cvta_generic_to_shared(dctx + row * ROWP + c4 * 4);
        int ok = (n0 + row < NCTX) ? 16 : 0;
        cpasync16(dst, src, ok);
    }
    if (t < 32) {
        const int* srcm = mask + (size_t)b * NCTX + n0 + t * 4;
        uint32_t dst = (uint32_t)__cvta_generic_to_shared(dmask + t * 4);
        int ok = (n0 + t * 4 < NCTX) ? 16 : 0;
        cpasync16(dst, srcm, ok);
    }
    cp_commit();
}

// one d-step: c broadcast into all 8 head partial-pairs
__device__ __forceinline__ void stepA(float c, const float* qb,
                                      ull &h01, ull &h23, ull &h45, ull &h67) {
    float4 q0 = *(const float4*)(qb);
    float4 q1 = *(const float4*)(qb + 4);
    ull cc = f2pack(c, c);
    h01 = ffma2(cc, f2pack(q0.x, q0.y), h01);
    h23 = ffma2(cc, f2pack(q0.z, q0.w), h23);
    h45 = ffma2(cc, f2pack(q1.x, q1.y), h45);
    h67 = ffma2(cc, f2pack(q1.z, q1.w), h67);
}

extern __shared__ float S[];

__global__ void __launch_bounds__(TPB, 1)
pointer_attn_kernel(const float* __restrict__ state_t,
                    const float* __restrict__ context,
                    const int*   __restrict__ mask,
                    const float* __restrict__ Wq,
                    const float* __restrict__ Wk_mha,
                    const float* __restrict__ Wv,
                    const float* __restrict__ Wfc,
                    const float* __restrict__ Wk,
                    const int*   __restrict__ Tptr,
                    float*       __restrict__ out)
{
    const int b = blockIdx.x;
    const int t = threadIdx.x;
    const float NEG_INF = __int_as_float(0xff800000u);

    float* sqkT  = S + OFF_QKT;
    float* se    = S + OFF_E;
    float* swmax = S + OFF_WMAX;
    float* swls  = S + OFF_WLS;
    float* sc    = S + OFF_C;
    float* sx    = S + OFF_X;
    float* sxf   = S + OFF_XF;
    float* sz    = S + OFF_Z;
    float* sstate= S + OFF_STATE;
    float* sq    = S + OFF_Q;
    float* su    = S + OFF_U;
    float* sred  = S + OFF_RED;

    issue_tile(0, b, context, mask, S, t);

    if (t < 384) sstate[t] = state_t[(size_t)b * 384 + t];
    if (t < 8) sred[R_MRUN + t] = NEG_INF;
    su[t] = NEG_INF;
    __syncthreads();

    // q[o] = state . Wq[:,o]
    {
        int o = t >> 3, kss = t & 7;
        float p = 0.f;
#pragma unroll
        for (int j = 0; j < 48; ++j) {
            int i = kss * 48 + j;
            p = fmaf(sstate[i], Wq[i * HID + o], p);
        }
        p += __shfl_xor_sync(0xffffffffu, p, 4);
        p += __shfl_xor_sync(0xffffffffu, p, 2);
        p += __shfl_xor_sync(0xffffffffu, p, 1);
        if (kss == 0) sq[o] = p;
    }
    __syncthreads();

    // qkT[d][h] = 0.25 * sum_j Wk_mha[d, 16h+j] * q[16h+j], swizzled layout
    {
        int d = t >> 3, h = t & 7;
        float p = 0.f;
#pragma unroll
        for (int j = 0; j < 16; ++j)
            p = fmaf(Wk_mha[d * HID + h * 16 + j], sq[h * 16 + j], p);
        sqkT[(d << 3) + ((d >> 4) << 2) + h] = 0.25f * p;
    }

    issue_tile(1, b, context, mask, S, t);
    __syncthreads();

    // ---- pass 1 ----
    ull acc[NH][2];
#pragma unroll
    for (int hh = 0; hh < NH; ++hh) { acc[hh][0] = 0ull; acc[hh][1] = 0ull; }
    float lrun = 0.f;

    const int n  = t >> 3, ks = t & 7;     // Phase A/B role
    const int wI = t >> 5, lane = t & 31;  // acc role
    const float* qb = sqkT + 132 * ks;

    for (int tile = 0; tile < NTILES; ++tile) {
        const float* C = S + ((tile & 1) ? OFF_CTX1 : OFF_CTX0);
        const int*   M = (const int*)(S + OFF_MASK) + (tile & 1) * 128;

        if (tile + 2 < NTILES) { cp_wait<1>(); }
        else                   { cp_wait<0>(); }
        __syncthreads();   // bar A: buffer ready, prev acc done

        // ---- Phase A: ctx read once, partials for all 8 heads ----
        float comp;
        bool dead;
        {
            const float4* crow = (const float4*)(C + n * ROWP + ks * 16);
            ull h01 = 0ull, h23 = 0ull, h45 = 0ull, h67 = 0ull;
            float4 cA = crow[0], cB = crow[1];
            stepA(cA.x, qb + 0,  h01, h23, h45, h67);
            stepA(cA.y, qb + 8,  h01, h23, h45, h67);
            stepA(cA.z, qb + 16, h01, h23, h45, h67);
            stepA(cA.w, qb + 24, h01, h23, h45, h67);
            stepA(cB.x, qb + 32, h01, h23, h45, h67);
            stepA(cB.y, qb + 40, h01, h23, h45, h67);
            stepA(cB.z, qb + 48, h01, h23, h45, h67);
            stepA(cB.w, qb + 56, h01, h23, h45, h67);
            cA = crow[2]; cB = crow[3];
            stepA(cA.x, qb + 64, h01, h23, h45, h67);
            stepA(cA.y, qb + 72, h01, h23, h45, h67);
            stepA(cA.z, qb + 80, h01, h23, h45, h67);
            stepA(cA.w, qb + 88, h01, h23, h45, h67);
            stepA(cB.x, qb + 96,  h01, h23, h45, h67);
            stepA(cB.y, qb + 104, h01, h23, h45, h67);
            stepA(cB.z, qb + 112, h01, h23, h45, h67);
            stepA(cB.w, qb + 120, h01, h23, h45, h67);

            float p0, p1, p2, p3, p4, p5, p6, p7;
            f2unpack(h01, p0, p1); f2unpack(h23, p2, p3);
            f2unpack(h45, p4, p5); f2unpack(h67, p6, p7);

            // 7-shfl transpose-reduce over the 8 ks-slices: thread ks ends with head ks
            {
                bool hi = (ks & 4) != 0;
                float k0 = hi ? p4 : p0, k1 = hi ? p5 : p1, k2 = hi ? p6 : p2, k3 = hi ? p7 : p3;
                float s0 = hi ? p0 : p4, s1 = hi ? p1 : p5, s2 = hi ? p2 : p6, s3 = hi ? p3 : p7;
                p0 = k0 + __shfl_xor_sync(0xffffffffu, s0, 4);
                p1 = k1 + __shfl_xor_sync(0xffffffffu, s1, 4);
                p2 = k2 + __shfl_xor_sync(0xffffffffu, s2, 4);
                p3 = k3 + __shfl_xor_sync(0xffffffffu, s3, 4);
            }
            {
                bool hi = (ks & 2) != 0;
                float k0 = hi ? p2 : p0, k1 = hi ? p3 : p1;
                float s0 = hi ? p0 : p2, s1 = hi ? p1 : p3;
                p0 = k0 + __shfl_xor_sync(0xffffffffu, s0, 2);
                p1 = k1 + __shfl_xor_sync(0xffffffffu, s1, 2);
            }
            {
                bool hi = (ks & 1) != 0;
                float k0 = hi ? p1 : p0;
                float s0 = hi ? p0 : p1;
                p0 = k0 + __shfl_xor_sync(0xffffffffu, s0, 1);
            }
            comp = p0;

            int gn = tile * TN + n;
            dead = (gn >= NCTX) || (M[n] != 0);
            if (dead) comp = NEG_INF;

            // per-warp max over this warp's 4 rows for head ks
            float m = comp;
            m = fmaxf(m, __shfl_xor_sync(0xffffffffu, m, 8));
            m = fmaxf(m, __shfl_xor_sync(0xffffffffu, m, 16));
            if (lane < 8) swmax[wI * 8 + lane] = m;
        }
        __syncthreads();   // bar B

        // merge 32 warp-maxes per head, update running max/scale
        if (t < 256) {
            int h = t >> 5, w = lane;
            float v = swmax[w * 8 + h];
            v = fmaxf(v, __shfl_xor_sync(0xffffffffu, v, 16));
            v = fmaxf(v, __shfl_xor_sync(0xffffffffu, v, 8));
            v = fmaxf(v, __shfl_xor_sync(0xffffffffu, v, 4));
            v = fmaxf(v, __shfl_xor_sync(0xffffffffu, v, 2));
            v = fmaxf(v, __shfl_xor_sync(0xffffffffu, v, 1));
            if (lane == 0) {
                float mo = sred[R_MRUN + h];
                float mn = fmaxf(mo, v);
                sred[R_MNEW + h]  = mn;
                sred[R_SCALE + h] = __expf(mo - mn);  // 1 if equal, 0 if mo=-inf
                sred[R_MRUN + h]  = mn;
            }
        }
        __syncthreads();   // bar C

        // ---- Phase B: e from register comp ----
        {
            float mn  = sred[R_MNEW + ks];
            float scl = sred[R_SCALE + ks];
            float e = dead ? 0.f : __expf(comp - mn);
            se[ks * ROWP + n] = e;
            lrun = lrun * scl + e;
        }
        __syncthreads();   // bar D

        // ---- acc: c_h += e[h][n] * ctx[n][:] ----
        {
#pragma unroll
            for (int hh = 0; hh < NH; ++hh) {
                float scl = sred[R_SCALE + hh];
                ull s2 = f2pack(scl, scl);
                acc[hh][0] = fmul2(acc[hh][0], s2);
                acc[hh][1] = fmul2(acc[hh][1], s2);
            }
#pragma unroll
            for (int r = 0; r < 4; ++r) {
                int nn = wI * 4 + r;
                float4 cv = *(const float4*)(C + nn * ROWP + lane * 4);
                ull c01 = f2pack(cv.x, cv.y), c23 = f2pack(cv.z, cv.w);
#pragma unroll
                for (int hh = 0; hh < NH; ++hh) {
                    float e = se[hh * ROWP + nn];
                    ull e2 = f2pack(e, e);
                    acc[hh][0] = ffma2(c01, e2, acc[hh][0]);
                    acc[hh][1] = ffma2(c23, e2, acc[hh][1]);
                }
            }
        }
        __syncthreads();   // bar E: all done reading buffer

        if (tile + 2 < NTILES) issue_tile(tile + 2, b, context, mask, S, t);
    }
    __syncthreads();

    // ---- reduce acc partials (scratch = both ctx buffers) + l partials ----
    {
        float* base = S + OFF_CTX0 + wI * (NH * DCTX);
#pragma unroll
        for (int hh = 0; hh < NH; ++hh) {
            float x0, x1, x2, x3;
            f2unpack(acc[hh][0], x0, x1);
            f2unpack(acc[hh][1], x2, x3);
            *(float4*)(base + hh * DCTX + lane * 4) = make_float4(x0, x1, x2, x3);
        }
        float lv = lrun;
        lv += __shfl_xor_sync(0xffffffffu, lv, 8);
        lv += __shfl_xor_sync(0xffffffffu, lv, 16);
        if (lane < 8) swls[wI * 8 + lane] = lv;
    }
    __syncthreads();
    {
        int hh = t >> 7, d = t & 127;
        float s = 0.f;
#pragma unroll
        for (int w = 0; w < 32; ++w) s += S[OFF_CTX0 + w * (NH * DCTX) + hh * DCTX + d];
        sc[hh * DCTX + d] = s;
    }
    if (t < 256) {
        int h = t >> 5, w = lane;
        float v = swls[w * 8 + h];
        v += __shfl_xor_sync(0xffffffffu, v, 16);
        v += __shfl_xor_sync(0xffffffffu, v, 8);
        v += __shfl_xor_sync(0xffffffffu, v, 4);
        v += __shfl_xor_sync(0xffffffffu, v, 2);
        v += __shfl_xor_sync(0xffffffffu, v, 1);
        if (lane == 0) sred[R_LRUN + h] = v;
    }
    __syncthreads();

    issue_tile(0, b, context, mask, S, t);

    // x[o] = (1/l_h) * sum_d c[h][d] * Wv[d,o]
    {
        int o = t >> 3, kss = t & 7, hh = o >> 4;
        float p = 0.f;
#pragma unroll
        for (int j = 0; j < 16; ++j) {
            int d = kss * 16 + j;
            p = fmaf(sc[hh * DCTX + d], Wv[d * HID + o], p);
        }
        p += __shfl_xor_sync(0xffffffffu, p, 4);
        p += __shfl_xor_sync(0xffffffffu, p, 2);
        p += __shfl_xor_sync(0xffffffffu, p, 1);
        if (kss == 0) sx[o] = p / sred[R_LRUN + hh];
    }
    __syncthreads();
    // xf = x @ Wfc
    {
        int o = t >> 3, kss = t & 7;
        float p = 0.f;
#pragma unroll
        for (int j = 0; j < 16; ++j) {
            int i = kss * 16 + j;
            p = fmaf(sx[i], Wfc[i * HID + o], p);
        }
        p += __shfl_xor_sync(0xffffffffu, p, 4);
        p += __shfl_xor_sync(0xffffffffu, p, 2);
        p += __shfl_xor_sync(0xffffffffu, p, 1);
        if (kss == 0) sxf[o] = p;
    }
    __syncthreads();
    // z[d] = (1/sqrt(HID)) * sum_o Wk[d,o] * xf[o]
    {
        int d = t >> 3, kss = t & 7;
        float p = 0.f;
#pragma unroll
        for (int j = 0; j < 16; ++j) {
            int o = kss * 16 + j;
            p = fmaf(Wk[d * HID + o], sxf[o], p);
        }
        p += __shfl_xor_sync(0xffffffffu, p, 4);
        p += __shfl_xor_sync(0xffffffffu, p, 2);
        p += __shfl_xor_sync(0xffffffffu, p, 1);
        if (kss == 0) sz[d] = 0.08838834764831845f * p;
    }
    issue_tile(1, b, context, mask, S, t);
    __syncthreads();

    // ---- pass 2: u[n] = 5*tanh(ctx[n].z), masked ----
    for (int tile = 0; tile < NTILES; ++tile) {
        const float* C = S + ((tile & 1) ? OFF_CTX1 : OFF_CTX0);
        const int*   M = (const int*)(S + OFF_MASK) + (tile & 1) * 128;

        if (tile + 2 < NTILES) { cp_wait<1>(); }
        else                   { cp_wait<0>(); }
        __syncthreads();

        {
            const float4* cr = (const float4*)(C + n * ROWP + ks * 16);
            const float4* zr = (const float4*)(sz + ks * 16);
            float p = 0.f;
#pragma unroll
            for (int i = 0; i < 4; ++i) {
                float4 a = cr[i], z = zr[i];
                p = fmaf(a.x, z.x, p); p = fmaf(a.y, z.y, p);
                p = fmaf(a.z, z.z, p); p = fmaf(a.w, z.w, p);
            }
            p += __shfl_xor_sync(0xffffffffu, p, 4);
            p += __shfl_xor_sync(0xffffffffu, p, 2);
            p += __shfl_xor_sync(0xffffffffu, p, 1);
            if (ks == 0) {
                int gn = tile * TN + n;
                if (gn < NCTX) su[gn] = (M[n] != 0) ? NEG_INF : 5.f * tanhf(p);
            }
        }
        __syncthreads();

        if (tile + 2 < NTILES) issue_tile(tile + 2, b, context, mask, S, t);
    }
    __syncthreads();

    // ---- final masked softmax over u ----
    {
        float v = su[t];
        v = fmaxf(v, __shfl_xor_sync(0xffffffffu, v, 16));
        v = fmaxf(v, __shfl_xor_sync(0xffffffffu, v, 8));
        v = fmaxf(v, __shfl_xor_sync(0xffffffffu, v, 4));
        v = fmaxf(v, __shfl_xor_sync(0xffffffffu, v, 2));
        v = fmaxf(v, __shfl_xor_sync(0xffffffffu, v, 1));
        if (lane == 0) sred[R_WARP + wI] = v;
    }
    __syncthreads();
    if (t < 32) {
        float v = sred[R_WARP + t];
        v = fmaxf(v, __shfl_xor_sync(0xffffffffu, v, 16));
        v = fmaxf(v, __shfl_xor_sync(0xffffffffu, v, 8));
        v = fmaxf(v, __shfl_xor_sync(0xffffffffu, v, 4));
        v = fmaxf(v, __shfl_xor_sync(0xffffffffu, v, 2));
        v = fmaxf(v, __shfl_xor_sync(0xffffffffu, v, 1));
        if (t == 0) sred[R_UMAX] = v;
    }
    __syncthreads();

    float invT;
    {
        int iv = Tptr[0];
        float Tv = (iv >= 1 && iv <= 1000000) ? (float)iv : __int_as_float(iv);
        if (!(Tv > 0.f)) Tv = 1.f;
        invT = 1.f / Tv;
    }
    float umax = sred[R_UMAX];
    float e = __expf((su[t] - umax) * invT);
    {
        float v = e;
        v += __shfl_xor_sync(0xffffffffu, v, 16);
        v += __shfl_xor_sync(0xffffffffu, v, 8);
        v += __shfl_xor_sync(0xffffffffu, v, 4);
        v += __shfl_xor_sync(0xffffffffu, v, 2);
        v += __shfl_xor_sync(0xffffffffu, v, 1);
        if (lane == 0) sred[R_WARP + wI] = v;
    }
    __syncthreads();
    if (t < 32) {
        float v = sred[R_WARP + t];
        v += __shfl_xor_sync(0xffffffffu, v, 16);
        v += __shfl_xor_sync(0xffffffffu, v, 8);
        v += __shfl_xor_sync(0xffffffffu, v, 4);
        v += __shfl_xor_sync(0xffffffffu, v, 2);
        v += __shfl_xor_sync(0xffffffffu, v, 1);
        if (t == 0) sred[R_USUM] = v;
    }
    __syncthreads();

    if (t < NCTX) out[(size_t)b * NCTX + t] = e / sred[R_USUM];
}

extern "C" void kernel_launch(void* const* d_in, const int* in_sizes, int n_in,
                              void* d_out, int out_size)
{
    const float* state_t = (const float*)d_in[0];
    const float* context = (const float*)d_in[1];
    const int*   mask    = (const int*)d_in[2];
    const float* Wq      = (const float*)d_in[3];
    const float* Wk_mha  = (const float*)d_in[4];
    const float* Wv      = (const float*)d_in[5];
    const float* Wfc     = (const float*)d_in[6];
    const float* Wk      = (const float*)d_in[7];
    const int*   Tptr    = (const int*)d_in[8];

    cudaFuncSetAttribute(pointer_attn_kernel,
                         cudaFuncAttributeMaxDynamicSharedMemorySize, SMEM_BYTES);
    pointer_attn_kernel<<<BATCH, TPB, SMEM_BYTES>>>(
        state_t, context, mask, Wq, Wk_mha, Wv, Wfc, Wk, Tptr, (float*)d_out);
}

// round 3
// speedup vs baseline: 1.2892x; 1.2892x over previous
#include <cuda_runtime.h>
#include <cstdint>

#define BATCH 512
#define NCTX  1000
#define DCTX  128
#define NH    8
#define HID   128
#define TN    64
#define NTILES 16
#define TPB   512
#define ROWP  132

// ---- smem layout (float offsets) ----
#define OFF_CTX0   0        // 64*132 = 8448
#define OFF_CTX1   8448
#define OFF_QKT    16896    // 1056 swizzled qkT
#define OFF_WLS    17952    // 128 (16 warps x 8 heads)
#define OFF_C      18080    // 1024
#define OFF_X      19104    // 128
#define OFF_XF     19232    // 128
#define OFF_Z      19360    // 128
#define OFF_STATE  19488    // 384
#define OFF_Q      19872    // 128
#define OFF_U      20000    // 1024
#define OFF_MASK   21024    // 128 ints (2 x 64)
#define OFF_RED    21152    // 64
#define SMEM_FLOATS 21216
#define SMEM_BYTES  (SMEM_FLOATS * 4)

#define R_LRUN  0
#define R_WARP  8
#define R_UMAX  24
#define R_USUM  25

typedef unsigned long long ull;

__device__ __forceinline__ ull f2pack(float lo, float hi) {
    ull r; asm("mov.b64 %0, {%1,%2};" : "=l"(r) : "f"(lo), "f"(hi)); return r;
}
__device__ __forceinline__ void f2unpack(ull v, float &lo, float &hi) {
    asm("mov.b64 {%0,%1}, %2;" : "=f"(lo), "=f"(hi) : "l"(v));
}
__device__ __forceinline__ ull ffma2(ull a, ull b, ull c) {
    ull d; asm("fma.rn.f32x2 %0, %1, %2, %3;" : "=l"(d) : "l"(a), "l"(b), "l"(c)); return d;
}

__device__ __forceinline__ void cpasync16(uint32_t dst, const void* src, int srcbytes) {
    asm volatile("cp.async.cg.shared.global [%0], [%1], 16, %2;"
                 :: "r"(dst), "l"(src), "r"(srcbytes));
}
__device__ __forceinline__ void cp_commit() { asm volatile("cp.async.commit_group;"); }
template <int NG> __device__ __forceinline__ void cp_wait() {
    asm volatile("cp.async.wait_group %0;" :: "n"(NG));
}

__device__ __forceinline__ void issue_tile(int tile, int b, const float* __restrict__ context,
                                           const int* __restrict__ mask,
                                           float* S, int t) {
    const int bufi = tile & 1;
    float* dctx = S + (bufi ? OFF_CTX1 : OFF_CTX0);
    int*   dmask = (int*)(S + OFF_MASK) + bufi * TN;
    const int n0 = tile * TN;
#pragma unroll
    for (int k = 0; k < 4; ++k) {
        int idx = t + k * TPB;              // 0..2047
        int row = idx >> 5, c4 = idx & 31;
        const float* src = context + ((size_t)b * NCTX + (size_t)(n0 + row)) * DCTX + c4 * 4;
        uint32_t dst = (uint32_t)__cvta_generic_to_shared(dctx + row * ROWP + c4 * 4);
        int ok = (n0 + row < NCTX) ? 16 : 0;
        cpasync16(dst, src, ok);
    }
    if (t < 16) {
        const int* srcm = mask + (size_t)b * NCTX + n0 + t * 4;
        uint32_t dst = (uint32_t)__cvta_generic_to_shared(dmask + t * 4);
        int ok = (n0 + t * 4 < NCTX) ? 16 : 0;
        cpasync16(dst, srcm, ok);
    }
    cp_commit();
}

extern __shared__ float S[];

__global__ void __launch_bounds__(TPB, 2)
pointer_attn_kernel(const float* __restrict__ state_t,
                    const float* __restrict__ context,
                    const int*   __restrict__ mask,
                    const float* __restrict__ Wq,
                    const float* __restrict__ Wk_mha,
                    const float* __restrict__ Wv,
                    const float* __restrict__ Wfc,
                    const float* __restrict__ Wk,
                    const int*   __restrict__ Tptr,
                    float*       __restrict__ out)
{
    const int b = blockIdx.x;
    const int t = threadIdx.x;
    const float NEG_INF = __int_as_float(0xff800000u);

    float* sqkT  = S + OFF_QKT;
    float* swls  = S + OFF_WLS;
    float* sc    = S + OFF_C;
    float* sx    = S + OFF_X;
    float* sxf   = S + OFF_XF;
    float* sz    = S + OFF_Z;
    float* sstate= S + OFF_STATE;
    float* sq    = S + OFF_Q;
    float* su    = S + OFF_U;
    float* sred  = S + OFF_RED;

    issue_tile(0, b, context, mask, S, t);

    if (t < 384) sstate[t] = state_t[(size_t)b * 384 + t];
    su[t] = NEG_INF;
    su[t + 512] = NEG_INF;
    __syncthreads();

    // q[o] = state . Wq[:,o]   (4-way split-K)
    {
        int o = t >> 2, k4 = t & 3;
        float p = 0.f;
#pragma unroll
        for (int j = 0; j < 96; ++j) {
            int i = k4 * 96 + j;
            p = fmaf(sstate[i], Wq[i * HID + o], p);
        }
        p += __shfl_xor_sync(0xffffffffu, p, 2);
        p += __shfl_xor_sync(0xffffffffu, p, 1);
        if (k4 == 0) sq[o] = p;
    }
    __syncthreads();

    // qkT[d][h] swizzled: off = d*8 + (d>>4)*4 + h  (conflict-free for Phase A)
#pragma unroll
    for (int it = 0; it < 2; ++it) {
        int d = (t >> 3) + it * 64, h = t & 7;
        float p = 0.f;
#pragma unroll
        for (int j = 0; j < 16; ++j)
            p = fmaf(Wk_mha[d * HID + h * 16 + j], sq[h * 16 + j], p);
        sqkT[(d << 3) + ((d >> 4) << 2) + h] = 0.25f * p;
    }

    issue_tile(1, b, context, mask, S, t);
    __syncthreads();

    // ---- pass 1: no-max softmax (exp direct) + weighted-context accumulation ----
    ull acc[NH][2];
#pragma unroll
    for (int hh = 0; hh < NH; ++hh) { acc[hh][0] = 0ull; acc[hh][1] = 0ull; }
    float lrun = 0.f;

    const int n  = t >> 3, ks = t & 7;     // Phase A role: row n, d-slice & head ks
    const int wI = t >> 5, lane = t & 31;  // acc role: warp rows wI*4..+3
    const float* qbase = sqkT + (ks << 7) + (ks << 2);  // d = ks*16 start

    for (int tile = 0; tile < NTILES; ++tile) {
        const float* C = S + ((tile & 1) ? OFF_CTX1 : OFF_CTX0);
        const int*   M = (const int*)(S + OFF_MASK) + (tile & 1) * TN;

        if (tile + 2 < NTILES) { cp_wait<1>(); }
        else                   { cp_wait<0>(); }
        __syncthreads();   // bar A: buffer ready

        // ---- Phase A: comp partials for all 8 heads (scalar FFMA, ctx read once)
        float cv[16];
        {
            const float4* crow = (const float4*)(C + n * ROWP + ks * 16);
            *(float4*)(cv + 0)  = crow[0];
            *(float4*)(cv + 4)  = crow[1];
            *(float4*)(cv + 8)  = crow[2];
            *(float4*)(cv + 12) = crow[3];
        }
        float p0 = 0.f, p1 = 0.f, p2 = 0.f, p3 = 0.f;
        float p4 = 0.f, p5 = 0.f, p6 = 0.f, p7 = 0.f;
#pragma unroll
        for (int j = 0; j < 16; ++j) {
            const float4* qp = (const float4*)(qbase + j * 8);
            float4 qa = qp[0], qb4 = qp[1];
            float c = cv[j];
            p0 = fmaf(c, qa.x, p0);  p1 = fmaf(c, qa.y, p1);
            p2 = fmaf(c, qa.z, p2);  p3 = fmaf(c, qa.w, p3);
            p4 = fmaf(c, qb4.x, p4); p5 = fmaf(c, qb4.y, p5);
            p6 = fmaf(c, qb4.z, p6); p7 = fmaf(c, qb4.w, p7);
        }

        // 7-shfl transpose-reduce: thread ks ends with comp for head ks
        {
            bool hi = (ks & 4) != 0;
            float k0 = hi ? p4 : p0, k1 = hi ? p5 : p1, k2 = hi ? p6 : p2, k3 = hi ? p7 : p3;
            float s0 = hi ? p0 : p4, s1 = hi ? p1 : p5, s2 = hi ? p2 : p6, s3 = hi ? p3 : p7;
            p0 = k0 + __shfl_xor_sync(0xffffffffu, s0, 4);
            p1 = k1 + __shfl_xor_sync(0xffffffffu, s1, 4);
            p2 = k2 + __shfl_xor_sync(0xffffffffu, s2, 4);
            p3 = k3 + __shfl_xor_sync(0xffffffffu, s3, 4);
        }
        {
            bool hi = (ks & 2) != 0;
            float k0 = hi ? p2 : p0, k1 = hi ? p3 : p1;
            float s0 = hi ? p0 : p2, s1 = hi ? p1 : p3;
            p0 = k0 + __shfl_xor_sync(0xffffffffu, s0, 2);
            p1 = k1 + __shfl_xor_sync(0xffffffffu, s1, 2);
        }
        {
            bool hi = (ks & 1) != 0;
            float k0 = hi ? p1 : p0;
            float s0 = hi ? p0 : p1;
            p0 = k0 + __shfl_xor_sync(0xffffffffu, s0, 1);
        }
        float comp = p0;

        int gn = tile * TN + n;
        bool dead = (gn >= NCTX) || (M[n] != 0);
        float e = dead ? 0.f : __expf(comp);
        lrun += e;

        // ---- acc: c_h += e[h][nn] * ctx[nn][:] ; e comes from this warp via shfl
#pragma unroll
        for (int r = 0; r < 4; ++r) {
            int nn = wI * 4 + r;
            float4 cvv = *(const float4*)(C + nn * ROWP + lane * 4);
            ull c01 = f2pack(cvv.x, cvv.y), c23 = f2pack(cvv.z, cvv.w);
#pragma unroll
            for (int hh = 0; hh < NH; ++hh) {
                float ev = __shfl_sync(0xffffffffu, e, (r << 3) | hh);
                ull e2 = f2pack(ev, ev);
                acc[hh][0] = ffma2(c01, e2, acc[hh][0]);
                acc[hh][1] = ffma2(c23, e2, acc[hh][1]);
            }
        }
        __syncthreads();   // bar B: done reading buffer

        if (tile + 2 < NTILES) issue_tile(tile + 2, b, context, mask, S, t);
    }
    __syncthreads();

    // ---- reduce acc partials (scratch = ctx buffers) + l partials ----
    {
        float* base = S + OFF_CTX0 + wI * (NH * DCTX);
#pragma unroll
        for (int hh = 0; hh < NH; ++hh) {
            float x0, x1, x2, x3;
            f2unpack(acc[hh][0], x0, x1);
            f2unpack(acc[hh][1], x2, x3);
            *(float4*)(base + hh * DCTX + lane * 4) = make_float4(x0, x1, x2, x3);
        }
        float lv = lrun;
        lv += __shfl_xor_sync(0xffffffffu, lv, 8);
        lv += __shfl_xor_sync(0xffffffffu, lv, 16);
        if (lane < 8) swls[wI * 8 + lane] = lv;
    }
    __syncthreads();
#pragma unroll
    for (int it = 0; it < 2; ++it) {
        int idx = t + it * 512;
        int hh = idx >> 7, d = idx & 127;
        float s = 0.f;
#pragma unroll
        for (int w = 0; w < 16; ++w) s += S[OFF_CTX0 + w * (NH * DCTX) + hh * DCTX + d];
        sc[hh * DCTX + d] = s;
    }
    if (t < 8) {
        float s = 0.f;
#pragma unroll
        for (int w = 0; w < 16; ++w) s += swls[w * 8 + t];
        sred[R_LRUN + t] = s;
    }
    __syncthreads();

    // scratch free — start pass-2 prefetch under the small matvecs
    issue_tile(0, b, context, mask, S, t);

    // x[o] = (1/l_h) * sum_d c[h][d] * Wv[d,o]
    {
        int o = t >> 2, k4 = t & 3, hh = o >> 4;
        float p = 0.f;
#pragma unroll
        for (int j = 0; j < 32; ++j) {
            int d = k4 * 32 + j;
            p = fmaf(sc[hh * DCTX + d], Wv[d * HID + o], p);
        }
        p += __shfl_xor_sync(0xffffffffu, p, 2);
        p += __shfl_xor_sync(0xffffffffu, p, 1);
        if (k4 == 0) sx[o] = p / sred[R_LRUN + hh];
    }
    __syncthreads();
    // xf = x @ Wfc
    {
        int o = t >> 2, k4 = t & 3;
        float p = 0.f;
#pragma unroll
        for (int j = 0; j < 32; ++j) {
            int i = k4 * 32 + j;
            p = fmaf(sx[i], Wfc[i * HID + o], p);
        }
        p += __shfl_xor_sync(0xffffffffu, p, 2);
        p += __shfl_xor_sync(0xffffffffu, p, 1);
        if (k4 == 0) sxf[o] = p;
    }
    __syncthreads();
    // z[d] = (1/sqrt(HID)) * sum_o Wk[d,o] * xf[o]
    {
        int d = t >> 2, k4 = t & 3;
        float p = 0.f;
#pragma unroll
        for (int j = 0; j < 32; ++j) {
            int o = k4 * 32 + j;
            p = fmaf(Wk[d * HID + o], sxf[o], p);
        }
        p += __shfl_xor_sync(0xffffffffu, p, 2);
        p += __shfl_xor_sync(0xffffffffu, p, 1);
        if (k4 == 0) sz[d] = 0.08838834764831845f * p;
    }
    issue_tile(1, b, context, mask, S, t);
    __syncthreads();

    // preload this thread's z slice into registers (tile-invariant)
    float4 zr0 = ((const float4*)(sz + ks * 16))[0];
    float4 zr1 = ((const float4*)(sz + ks * 16))[1];
    float4 zr2 = ((const float4*)(sz + ks * 16))[2];
    float4 zr3 = ((const float4*)(sz + ks * 16))[3];

    // ---- pass 2: u[n] = 5*tanh(ctx[n].z), masked ----
    for (int tile = 0; tile < NTILES; ++tile) {
        const float* C = S + ((tile & 1) ? OFF_CTX1 : OFF_CTX0);
        const int*   M = (const int*)(S + OFF_MASK) + (tile & 1) * TN;

        if (tile + 2 < NTILES) { cp_wait<1>(); }
        else                   { cp_wait<0>(); }
        __syncthreads();

        {
            const float4* cr = (const float4*)(C + n * ROWP + ks * 16);
            float4 a0 = cr[0], a1 = cr[1], a2 = cr[2], a3 = cr[3];
            float p = 0.f;
            p = fmaf(a0.x, zr0.x, p); p = fmaf(a0.y, zr0.y, p);
            p = fmaf(a0.z, zr0.z, p); p = fmaf(a0.w, zr0.w, p);
            p = fmaf(a1.x, zr1.x, p); p = fmaf(a1.y, zr1.y, p);
            p = fmaf(a1.z, zr1.z, p); p = fmaf(a1.w, zr1.w, p);
            p = fmaf(a2.x, zr2.x, p); p = fmaf(a2.y, zr2.y, p);
            p = fmaf(a2.z, zr2.z, p); p = fmaf(a2.w, zr2.w, p);
            p = fmaf(a3.x, zr3.x, p); p = fmaf(a3.y, zr3.y, p);
            p = fmaf(a3.z, zr3.z, p); p = fmaf(a3.w, zr3.w, p);
            p += __shfl_xor_sync(0xffffffffu, p, 4);
            p += __shfl_xor_sync(0xffffffffu, p, 2);
            p += __shfl_xor_sync(0xffffffffu, p, 1);
            if (ks == 0) {
                int gn = tile * TN + n;
                if (gn < NCTX) su[gn] = (M[n] != 0) ? NEG_INF : 5.f * tanhf(p);
            }
        }
        __syncthreads();

        if (tile + 2 < NTILES) issue_tile(tile + 2, b, context, mask, S, t);
    }
    __syncthreads();

    // ---- final masked softmax over u (each thread owns entries t and t+512) ----
    float ua = su[t], ub = su[t + 512];
    {
        float v = fmaxf(ua, ub);
        v = fmaxf(v, __shfl_xor_sync(0xffffffffu, v, 16));
        v = fmaxf(v, __shfl_xor_sync(0xffffffffu, v, 8));
        v = fmaxf(v, __shfl_xor_sync(0xffffffffu, v, 4));
        v = fmaxf(v, __shfl_xor_sync(0xffffffffu, v, 2));
        v = fmaxf(v, __shfl_xor_sync(0xffffffffu, v, 1));
        if (lane == 0) sred[R_WARP + wI] = v;
    }
    __syncthreads();
    if (t < 32) {
        float v = (t < 16) ? sred[R_WARP + t] : NEG_INF;
        v = fmaxf(v, __shfl_xor_sync(0xffffffffu, v, 8));
        v = fmaxf(v, __shfl_xor_sync(0xffffffffu, v, 4));
        v = fmaxf(v, __shfl_xor_sync(0xffffffffu, v, 2));
        v = fmaxf(v, __shfl_xor_sync(0xffffffffu, v, 1));
        if (t == 0) sred[R_UMAX] = v;
    }
    __syncthreads();

    float invT;
    {
        int iv = Tptr[0];
        float Tv = (iv >= 1 && iv <= 1000000) ? (float)iv : __int_as_float(iv);
        if (!(Tv > 0.f)) Tv = 1.f;
        invT = 1.f / Tv;
    }
    float umax = sred[R_UMAX];
    float ea = __expf((ua - umax) * invT);   // -inf -> 0
    float eb = __expf((ub - umax) * invT);
    {
        float v = ea + eb;
        v += __shfl_xor_sync(0xffffffffu, v, 16);
        v += __shfl_xor_sync(0xffffffffu, v, 8);
        v += __shfl_xor_sync(0xffffffffu, v, 4);
        v += __shfl_xor_sync(0xffffffffu, v, 2);
        v += __shfl_xor_sync(0xffffffffu, v, 1);
        if (lane == 0) sred[R_WARP + wI] = v;
    }
    __syncthreads();
    if (t < 32) {
        float v = (t < 16) ? sred[R_WARP + t] : 0.f;
        v += __shfl_xor_sync(0xffffffffu, v, 8);
        v += __shfl_xor_sync(0xffffffffu, v, 4);
        v += __shfl_xor_sync(0xffffffffu, v, 2);
        v += __shfl_xor_sync(0xffffffffu, v, 1);
        if (t == 0) sred[R_USUM] = v;
    }
    __syncthreads();

    float inv_sum = 1.f / sred[R_USUM];
    out[(size_t)b * NCTX + t] = ea * inv_sum;
    if (t + 512 < NCTX) out[(size_t)b * NCTX + t + 512] = eb * inv_sum;
}

extern "C" void kernel_launch(void* const* d_in, const int* in_sizes, int n_in,
                              void* d_out, int out_size)
{
    const float* state_t = (const float*)d_in[0];
    const float* context = (const float*)d_in[1];
    const int*   mask    = (const int*)d_in[2];
    const float* Wq      = (const float*)d_in[3];
    const float* Wk_mha  = (const float*)d_in[4];
    const float* Wv      = (const float*)d_in[5];
    const float* Wfc     = (const float*)d_in[6];
    const float* Wk      = (const float*)d_in[7];
    const int*   Tptr    = (const int*)d_in[8];

    cudaFuncSetAttribute(pointer_attn_kernel,
                         cudaFuncAttributeMaxDynamicSharedMemorySize, SMEM_BYTES);
    pointer_attn_kernel<<<BATCH, TPB, SMEM_BYTES>>>(
        state_t, context, mask, Wq, Wk_mha, Wv, Wfc, Wk, Tptr, (float*)d_out);
}

// round 6
// speedup vs baseline: 1.6421x; 1.2737x over previous
#include <cuda_runtime.h>
#include <cstdint>

#define BATCH  512
#define NCTX   1000
#define DCTX   128
#define NH     8
#define HID    128
#define TN     128
#define NTILES 8
#define TPB    512
#define NSTAGE 3

// ---- smem layout (float offsets) ----
#define OFF_CTX0   0            // 3 x 16384 (stages)
#define CTX_STRIDE 16384
#define OFF_QKT    49152        // 1024: qkT[d][h] = [d*8+h]
#define OFF_SE     50176        // 1024: e[row][h]
#define OFF_SWLS   51200        // 128
#define OFF_SC     51328        // 1024
#define OFF_SQ     52352        // 128
#define OFF_SX     52480        // 128
#define OFF_SXF    52608        // 128
#define OFF_SZ     52736        // 128
#define OFF_STATE  52864        // 384
#define OFF_SU     53248        // 1024
#define OFF_MASK   54272        // 3*128 ints
#define OFF_RED    54656        // 64
#define OFF_MBAR   54720        // 3 x u64 (8B aligned)
#define SMEM_FLOATS 54736
#define SMEM_BYTES  (SMEM_FLOATS * 4)

#define R_WARP 0
#define R_UMAX 16
#define R_USUM 17
#define R_L    32   // 8 per-head l sums

typedef unsigned long long ull;

__device__ __forceinline__ ull f2pack(float lo, float hi) {
    ull r; asm("mov.b64 %0, {%1,%2};" : "=l"(r) : "f"(lo), "f"(hi)); return r;
}
__device__ __forceinline__ void f2unpack(ull v, float &lo, float &hi) {
    asm("mov.b64 {%0,%1}, %2;" : "=f"(lo), "=f"(hi) : "l"(v));
}
__device__ __forceinline__ ull ffma2(ull a, ull b, ull c) {
    ull d; asm("fma.rn.f32x2 %0, %1, %2, %3;" : "=l"(d) : "l"(a), "l"(b), "l"(c)); return d;
}

// split-butterfly reduce: in[8] partials per lane (32 lanes), returns the full
// 32-lane sum of value index bitrev3(lane&7). 9 SHFL total.
__device__ __forceinline__ float split_butterfly8(const float* p, int lane) {
    bool h1 = (lane & 1) != 0;
    float k0 = h1 ? p[4] : p[0], k1 = h1 ? p[5] : p[1];
    float k2 = h1 ? p[6] : p[2], k3 = h1 ? p[7] : p[3];
    float s0 = h1 ? p[0] : p[4], s1 = h1 ? p[1] : p[5];
    float s2 = h1 ? p[2] : p[6], s3 = h1 ? p[3] : p[7];
    k0 += __shfl_xor_sync(0xffffffffu, s0, 1);
    k1 += __shfl_xor_sync(0xffffffffu, s1, 1);
    k2 += __shfl_xor_sync(0xffffffffu, s2, 1);
    k3 += __shfl_xor_sync(0xffffffffu, s3, 1);
    bool h2 = (lane & 2) != 0;
    float t0 = h2 ? k2 : k0, t1 = h2 ? k3 : k1;
    float u0 = h2 ? k0 : k2, u1 = h2 ? k1 : k3;
    t0 += __shfl_xor_sync(0xffffffffu, u0, 2);
    t1 += __shfl_xor_sync(0xffffffffu, u1, 2);
    bool h4 = (lane & 4) != 0;
    float v = h4 ? t1 : t0;
    float w = h4 ? t0 : t1;
    v += __shfl_xor_sync(0xffffffffu, w, 4);
    v += __shfl_xor_sync(0xffffffffu, v, 8);
    v += __shfl_xor_sync(0xffffffffu, v, 16);
    return v;
}
// index owned by lane after split_butterfly8
__device__ __forceinline__ int bitrev3(int l) {
    return ((l & 1) << 2) | (l & 2) | ((l >> 2) & 1);
}

// ---- mbarrier / bulk-copy helpers ----
__device__ __forceinline__ void mbar_init(uint32_t addr, uint32_t count) {
    asm volatile("mbarrier.init.shared.b64 [%0], %1;" :: "r"(addr), "r"(count) : "memory");
}
__device__ __forceinline__ void mbar_expect_tx(uint32_t addr, uint32_t bytes) {
    asm volatile("mbarrier.arrive.expect_tx.shared::cta.b64 _, [%0], %1;"
                 :: "r"(addr), "r"(bytes) : "memory");
}
__device__ __forceinline__ void bulk_g2s(uint32_t dst, const void* src, uint32_t bytes, uint32_t mbar) {
    asm volatile("cp.async.bulk.shared::cluster.global.mbarrier::complete_tx::bytes "
                 "[%0], [%1], %2, [%3];"
                 :: "r"(dst), "l"(src), "r"(bytes), "r"(mbar) : "memory");
}
__device__ __forceinline__ void fence_async() {
    asm volatile("fence.proxy.async.shared::cta;" ::: "memory");
}
__device__ __forceinline__ void mbar_wait(uint32_t mbar, uint32_t parity) {
    uint32_t done;
    asm volatile(
        "{\n\t.reg .pred p;\n\t"
        "mbarrier.try_wait.parity.acquire.cta.shared::cta.b64 p, [%1], %2;\n\t"
        "selp.b32 %0, 1, 0, p;\n\t}"
        : "=r"(done) : "r"(mbar), "r"(parity) : "memory");
    if (!done) {
        asm volatile(
            "{\n\t.reg .pred P1;\n\t"
            "WAIT_LOOP_%=:\n\t"
            "mbarrier.try_wait.parity.acquire.cta.shared::cta.b64 P1, [%0], %1, 0x989680;\n\t"
            "@P1 bra.uni WAIT_DONE_%=;\n\t"
            "bra.uni WAIT_LOOP_%=;\n\t"
            "WAIT_DONE_%=:\n\t}"
            :: "r"(mbar), "r"(parity) : "memory");
    }
}

extern __shared__ float S[];

__device__ __forceinline__ void issue_g(int g, int b, const float* __restrict__ context,
                                        const int* __restrict__ mask, uint32_t su32) {
    int tile  = (g < NTILES) ? g : g - NTILES;
    int stage = g % NSTAGE;
    int n0    = tile * TN;
    int rows  = NCTX - n0; if (rows > TN) rows = TN;
    uint32_t ctx_bytes  = (uint32_t)rows * DCTX * 4;
    uint32_t mask_bytes = (uint32_t)rows * 4;
    uint32_t mbar     = su32 + OFF_MBAR * 4 + stage * 8;
    uint32_t dst_ctx  = su32 + (OFF_CTX0 + stage * CTX_STRIDE) * 4;
    uint32_t dst_mask = su32 + OFF_MASK * 4 + stage * TN * 4;
    const float* src_ctx = context + (size_t)b * NCTX * DCTX + (size_t)n0 * DCTX;
    const int*   src_m   = mask + (size_t)b * NCTX + n0;
    mbar_expect_tx(mbar, ctx_bytes + mask_bytes);
    bulk_g2s(dst_ctx, src_ctx, ctx_bytes, mbar);
    bulk_g2s(dst_mask, src_m, mask_bytes, mbar);
}

__device__ __forceinline__ void wait_g(int g, uint32_t su32) {
    uint32_t mbar = su32 + OFF_MBAR * 4 + (g % NSTAGE) * 8;
    mbar_wait(mbar, (uint32_t)((g / NSTAGE) & 1));
}

__global__ void __launch_bounds__(TPB, 1)
pointer_attn_kernel(const float* __restrict__ state_t,
                    const float* __restrict__ context,
                    const int*   __restrict__ mask,
                    const float* __restrict__ Wq,
                    const float* __restrict__ Wk_mha,
                    const float* __restrict__ Wv,
                    const float* __restrict__ Wfc,
                    const float* __restrict__ Wk,
                    const int*   __restrict__ Tptr,
                    float*       __restrict__ out)
{
    const int b = blockIdx.x;
    const int t = threadIdx.x;
    const int wI = t >> 5, lane = t & 31;
    const float NEG_INF = __int_as_float(0xff800000u);
    const uint32_t su32 = (uint32_t)__cvta_generic_to_shared(S);

    float* sqkT  = S + OFF_QKT;
    float* se    = S + OFF_SE;
    float* swls  = S + OFF_SWLS;
    float* sc    = S + OFF_SC;
    float* sq    = S + OFF_SQ;
    float* sx    = S + OFF_SX;
    float* sxf   = S + OFF_SXF;
    float* sz    = S + OFF_SZ;
    float* sstate= S + OFF_STATE;
    float* su    = S + OFF_SU;
    float* sred  = S + OFF_RED;

    // ---- prologue: mbars + first 3 bulk loads ----
    if (t == 0) {
        mbar_init(su32 + OFF_MBAR * 4 + 0, 1);
        mbar_init(su32 + OFF_MBAR * 4 + 8, 1);
        mbar_init(su32 + OFF_MBAR * 4 + 16, 1);
    }
    __syncthreads();
    if (t == 0) {
        fence_async();
        issue_g(0, b, context, mask, su32);
        issue_g(1, b, context, mask, su32);
        issue_g(2, b, context, mask, su32);
    }

    if (t < 384) sstate[t] = state_t[(size_t)b * 384 + t];
    su[t] = NEG_INF;
    su[t + 512] = NEG_INF;
    __syncthreads();

    // q[o] = state . Wq[:,o]  (4-way split-K)
    {
        int o = t >> 2, k4 = t & 3;
        float p = 0.f;
#pragma unroll
        for (int j = 0; j < 96; ++j) {
            int i = k4 * 96 + j;
            p = fmaf(sstate[i], Wq[i * HID + o], p);
        }
        p += __shfl_xor_sync(0xffffffffu, p, 2);
        p += __shfl_xor_sync(0xffffffffu, p, 1);
        if (k4 == 0) sq[o] = p;
    }
    __syncthreads();

    // qkT[d][h] = 0.25 * sum_j Wk_mha[d][16h+j] q[16h+j]   (layout d*8+h)
#pragma unroll
    for (int it = 0; it < 2; ++it) {
        int d = (t >> 3) + it * 64, h = t & 7;
        float p = 0.f;
#pragma unroll
        for (int j = 0; j < 16; ++j)
            p = fmaf(Wk_mha[d * HID + h * 16 + j], sq[h * 16 + j], p);
        sqkT[d * 8 + h] = 0.25f * p;
    }
    __syncthreads();

    // ---- hoist this lane's qk block: qkp[dd][hp] = (qk[d][2hp], qk[d][2hp+1])
    ull qkp[4][4];
#pragma unroll
    for (int dd = 0; dd < 4; ++dd)
#pragma unroll
        for (int hp = 0; hp < 4; ++hp)
            qkp[dd][hp] = *(const ull*)(sqkT + (lane * 4 + dd) * 8 + hp * 2);

    const int hsel = bitrev3(lane & 7);

    // ---- pass 1: comp (lane partials + split butterfly) + exp + weighted-ctx acc ----
    ull acc[NH][2];
#pragma unroll
    for (int hh = 0; hh < NH; ++hh) { acc[hh][0] = 0ull; acc[hh][1] = 0ull; }
    float lrun = 0.f;

    for (int g = 0; g < NTILES; ++g) {
        wait_g(g, su32);
        const float* C = S + (g % NSTAGE) * CTX_STRIDE;
        const int*   M = (const int*)(S + OFF_MASK) + (g % NSTAGE) * TN;
        const int n0 = g * TN;

#pragma unroll
        for (int r = 0; r < 8; ++r) {
            const int nn = wI * 8 + r;
            float4 cv = *(const float4*)(C + nn * DCTX + lane * 4);

            // comp partials for 8 heads on this lane's 4-d chunk
            ull cc0 = f2pack(cv.x, cv.x), cc1 = f2pack(cv.y, cv.y);
            ull cc2 = f2pack(cv.z, cv.z), cc3 = f2pack(cv.w, cv.w);
            ull p01 = 0ull, p23 = 0ull, p45 = 0ull, p67 = 0ull;
            p01 = ffma2(cc0, qkp[0][0], p01); p23 = ffma2(cc0, qkp[0][1], p23);
            p45 = ffma2(cc0, qkp[0][2], p45); p67 = ffma2(cc0, qkp[0][3], p67);
            p01 = ffma2(cc1, qkp[1][0], p01); p23 = ffma2(cc1, qkp[1][1], p23);
            p45 = ffma2(cc1, qkp[1][2], p45); p67 = ffma2(cc1, qkp[1][3], p67);
            p01 = ffma2(cc2, qkp[2][0], p01); p23 = ffma2(cc2, qkp[2][1], p23);
            p45 = ffma2(cc2, qkp[2][2], p45); p67 = ffma2(cc2, qkp[2][3], p67);
            p01 = ffma2(cc3, qkp[3][0], p01); p23 = ffma2(cc3, qkp[3][1], p23);
            p45 = ffma2(cc3, qkp[3][2], p45); p67 = ffma2(cc3, qkp[3][3], p67);

            float pv[8];
            f2unpack(p01, pv[0], pv[1]); f2unpack(p23, pv[2], pv[3]);
            f2unpack(p45, pv[4], pv[5]); f2unpack(p67, pv[6], pv[7]);

            float compv = split_butterfly8(pv, lane);  // lane holds head hsel

            if (lane < 8) {
                bool dead = (n0 + nn >= NCTX) || (M[nn] != 0);
                float ev = dead ? 0.f : __expf(compv);
                lrun += ev;                 // this lane accumulates head hsel
                se[nn * 8 + hsel] = ev;
            }
            __syncwarp();
            float4 e03 = *(const float4*)(se + nn * 8);
            float4 e47 = *(const float4*)(se + nn * 8 + 4);

            // acc: c_h += e_h * ctx chunk
            ull c01 = f2pack(cv.x, cv.y), c23 = f2pack(cv.z, cv.w);
            ull e2;
            e2 = f2pack(e03.x, e03.x); acc[0][0] = ffma2(c01, e2, acc[0][0]); acc[0][1] = ffma2(c23, e2, acc[0][1]);
            e2 = f2pack(e03.y, e03.y); acc[1][0] = ffma2(c01, e2, acc[1][0]); acc[1][1] = ffma2(c23, e2, acc[1][1]);
            e2 = f2pack(e03.z, e03.z); acc[2][0] = ffma2(c01, e2, acc[2][0]); acc[2][1] = ffma2(c23, e2, acc[2][1]);
            e2 = f2pack(e03.w, e03.w); acc[3][0] = ffma2(c01, e2, acc[3][0]); acc[3][1] = ffma2(c23, e2, acc[3][1]);
            e2 = f2pack(e47.x, e47.x); acc[4][0] = ffma2(c01, e2, acc[4][0]); acc[4][1] = ffma2(c23, e2, acc[4][1]);
            e2 = f2pack(e47.y, e47.y); acc[5][0] = ffma2(c01, e2, acc[5][0]); acc[5][1] = ffma2(c23, e2, acc[5][1]);
            e2 = f2pack(e47.z, e47.z); acc[6][0] = ffma2(c01, e2, acc[6][0]); acc[6][1] = ffma2(c23, e2, acc[6][1]);
            e2 = f2pack(e47.w, e47.w); acc[7][0] = ffma2(c01, e2, acc[7][0]); acc[7][1] = ffma2(c23, e2, acc[7][1]);
        }
        __syncthreads();   // all warps done reading buffer
        if (t == 0 && g + 3 < NTILES) issue_g(g + 3, b, context, mask, su32);
    }

    // ---- reduce acc partials across 16 warps (scratch = stage-0 buffer) ----
    {
        float* scr = S + wI * 1024;   // [warp][h*128+d]
#pragma unroll
        for (int hh = 0; hh < NH; ++hh) {
            float x0, x1, x2, x3;
            f2unpack(acc[hh][0], x0, x1);
            f2unpack(acc[hh][1], x2, x3);
            *(float4*)(scr + hh * DCTX + lane * 4) = make_float4(x0, x1, x2, x3);
        }
        if (lane < 8) swls[wI * 8 + hsel] = lrun;
    }
    __syncthreads();
#pragma unroll
    for (int it = 0; it < 2; ++it) {
        int idx = t + it * 512;
        float s = 0.f;
#pragma unroll
        for (int w = 0; w < 16; ++w) s += S[w * 1024 + idx];
        sc[idx] = s;
    }
    if (t < 8) {
        float s = 0.f;
#pragma unroll
        for (int w = 0; w < 16; ++w) s += swls[w * 8 + t];
        sred[R_L + t] = s;
    }
    __syncthreads();

    // scratch consumed — fence generic->async, then prefetch pass-2 tiles;
    // the small matvecs below overlap these loads
    if (t == 0) {
        fence_async();
        issue_g(8, b, context, mask, su32);
        issue_g(9, b, context, mask, su32);
        issue_g(10, b, context, mask, su32);
    }

    // x[o] = (1/l_h) * sum_d c[h][d] * Wv[d][o]
    {
        int o = t >> 2, k4 = t & 3, hh = o >> 4;
        float p = 0.f;
#pragma unroll
        for (int j = 0; j < 32; ++j) {
            int d = k4 * 32 + j;
            p = fmaf(sc[hh * DCTX + d], Wv[d * HID + o], p);
        }
        p += __shfl_xor_sync(0xffffffffu, p, 2);
        p += __shfl_xor_sync(0xffffffffu, p, 1);
        if (k4 == 0) sx[o] = p / sred[R_L + hh];
    }
    __syncthreads();
    // xf = x @ Wfc
    {
        int o = t >> 2, k4 = t & 3;
        float p = 0.f;
#pragma unroll
        for (int j = 0; j < 32; ++j) {
            int i = k4 * 32 + j;
            p = fmaf(sx[i], Wfc[i * HID + o], p);
        }
        p += __shfl_xor_sync(0xffffffffu, p, 2);
        p += __shfl_xor_sync(0xffffffffu, p, 1);
        if (k4 == 0) sxf[o] = p;
    }
    __syncthreads();
    // z[d] = (1/sqrt(HID)) * sum_o Wk[d][o] * xf[o]
    {
        int d = t >> 2, k4 = t & 3;
        float p = 0.f;
#pragma unroll
        for (int j = 0; j < 32; ++j) {
            int o = k4 * 32 + j;
            p = fmaf(Wk[d * HID + o], sxf[o], p);
        }
        p += __shfl_xor_sync(0xffffffffu, p, 2);
        p += __shfl_xor_sync(0xffffffffu, p, 1);
        if (k4 == 0) sz[d] = 0.08838834764831845f * p;
    }
    __syncthreads();

    // hoist z chunk
    float4 zv = *(const float4*)(sz + lane * 4);
    ull z01 = f2pack(zv.x, zv.y), z23 = f2pack(zv.z, zv.w);

    // ---- pass 2: u[n] = 5*tanh(ctx[n].z), masked ----
    for (int g = NTILES; g < 2 * NTILES; ++g) {
        wait_g(g, su32);
        const float* C = S + (g % NSTAGE) * CTX_STRIDE;
        const int*   M = (const int*)(S + OFF_MASK) + (g % NSTAGE) * TN;
        const int n0 = (g - NTILES) * TN;

        float dr[8];
#pragma unroll
        for (int r = 0; r < 8; ++r) {
            const int nn = wI * 8 + r;
            float4 cv = *(const float4*)(C + nn * DCTX + lane * 4);
            ull c01 = f2pack(cv.x, cv.y), c23 = f2pack(cv.z, cv.w);
            ull s2 = ffma2(c01, z01, ffma2(c23, z23, 0ull));
            float a0, a1; f2unpack(s2, a0, a1);
            dr[r] = a0 + a1;
        }
        // one split butterfly over the 8 rows; lane holds row bitrev3(lane&7)
        float ud = split_butterfly8(dr, lane);

        if (lane < 8) {
            int nn2 = wI * 8 + hsel;       // hsel == bitrev3(lane) is the row here
            int gn2 = n0 + nn2;
            if (gn2 < NCTX) {
                int mrow = M[nn2];
                su[gn2] = (mrow != 0) ? NEG_INF : 5.f * tanhf(ud);
            }
        }
        __syncthreads();
        if (t == 0 && g + 3 < 2 * NTILES) issue_g(g + 3, b, context, mask, su32);
    }
    __syncthreads();

    // ---- final masked softmax over u ----
    float ua = su[t], ub = su[t + 512];
    {
        float v = fmaxf(ua, ub);
        v = fmaxf(v, __shfl_xor_sync(0xffffffffu, v, 16));
        v = fmaxf(v, __shfl_xor_sync(0xffffffffu, v, 8));
        v = fmaxf(v, __shfl_xor_sync(0xffffffffu, v, 4));
        v = fmaxf(v, __shfl_xor_sync(0xffffffffu, v, 2));
        v = fmaxf(v, __shfl_xor_sync(0xffffffffu, v, 1));
        if (lane == 0) sred[R_WARP + wI] = v;
    }
    __syncthreads();
    if (t < 32) {
        float v = (t < 16) ? sred[R_WARP + t] : NEG_INF;
        v = fmaxf(v, __shfl_xor_sync(0xffffffffu, v, 8));
        v = fmaxf(v, __shfl_xor_sync(0xffffffffu, v, 4));
        v = fmaxf(v, __shfl_xor_sync(0xffffffffu, v, 2));
        v = fmaxf(v, __shfl_xor_sync(0xffffffffu, v, 1));
        if (t == 0) sred[R_UMAX] = v;
    }
    __syncthreads();

    float invT;
    {
        int iv = Tptr[0];
        float Tv = (iv >= 1 && iv <= 1000000) ? (float)iv : __int_as_float(iv);
        if (!(Tv > 0.f)) Tv = 1.f;
        invT = 1.f / Tv;
    }
    float umax = sred[R_UMAX];
    float ea = __expf((ua - umax) * invT);
    float eb = __expf((ub - umax) * invT);
    {
        float v = ea + eb;
        v += __shfl_xor_sync(0xffffffffu, v, 16);
        v += __shfl_xor_sync(0xffffffffu, v, 8);
        v += __shfl_xor_sync(0xffffffffu, v, 4);
        v += __shfl_xor_sync(0xffffffffu, v, 2);
        v += __shfl_xor_sync(0xffffffffu, v, 1);
        if (lane == 0) sred[R_WARP + wI] = v;
    }
    __syncthreads();
    if (t < 32) {
        float v = (t < 16) ? sred[R_WARP + t] : 0.f;
        v += __shfl_xor_sync(0xffffffffu, v, 8);
        v += __shfl_xor_sync(0xffffffffu, v, 4);
        v += __shfl_xor_sync(0xffffffffu, v, 2);
        v += __shfl_xor_sync(0xffffffffu, v, 1);
        if (t == 0) sred[R_USUM] = v;
    }
    __syncthreads();

    float inv_sum = 1.f / sred[R_USUM];
    out[(size_t)b * NCTX + t] = ea * inv_sum;
    if (t + 512 < NCTX) out[(size_t)b * NCTX + t + 512] = eb * inv_sum;
}

extern "C" void kernel_launch(void* const* d_in, const int* in_sizes, int n_in,
                              void* d_out, int out_size)
{
    const float* state_t = (const float*)d_in[0];
    const float* context = (const float*)d_in[1];
    const int*   mask    = (const int*)d_in[2];
    const float* Wq      = (const float*)d_in[3];
    const float* Wk_mha  = (const float*)d_in[4];
    const float* Wv      = (const float*)d_in[5];
    const float* Wfc     = (const float*)d_in[6];
    const float* Wk      = (const float*)d_in[7];
    const int*   Tptr    = (const int*)d_in[8];

    cudaFuncSetAttribute(pointer_attn_kernel,
                         cudaFuncAttributeMaxDynamicSharedMemorySize, SMEM_BYTES);
    pointer_attn_kernel<<<BATCH, TPB, SMEM_BYTES>>>(
        state_t, context, mask, Wq, Wk_mha, Wv, Wfc, Wk, Tptr, (float*)d_out);
}

// round 7
// speedup vs baseline: 2.1235x; 1.2932x over previous
#include <cuda_runtime.h>
#include <cstdint>

#define BATCH 512
#define NCTX  1000
#define DCTX  128
#define NH    8
#define HID   128
#define TPB   128
#define RPW   256   // rows per warp

typedef unsigned long long ull;

__device__ __forceinline__ ull f2pack(float lo, float hi) {
    ull r; asm("mov.b64 %0, {%1,%2};" : "=l"(r) : "f"(lo), "f"(hi)); return r;
}
__device__ __forceinline__ void f2unpack(ull v, float &lo, float &hi) {
    asm("mov.b64 {%0,%1}, %2;" : "=f"(lo), "=f"(hi) : "l"(v));
}
__device__ __forceinline__ ull ffma2(ull a, ull b, ull c) {
    ull d; asm("fma.rn.f32x2 %0, %1, %2, %3;" : "=l"(d) : "l"(a), "l"(b), "l"(c)); return d;
}

// split-butterfly: p[8] partials per lane; returns full 32-lane sum of index
// bitrev3(lane&7), replicated to all 4 lanes sharing (lane&7). 9 SHFL.
__device__ __forceinline__ float split_butterfly8(const float* p, int lane) {
    bool h1 = (lane & 1) != 0;
    float k0 = h1 ? p[4] : p[0], k1 = h1 ? p[5] : p[1];
    float k2 = h1 ? p[6] : p[2], k3 = h1 ? p[7] : p[3];
    float s0 = h1 ? p[0] : p[4], s1 = h1 ? p[1] : p[5];
    float s2 = h1 ? p[2] : p[6], s3 = h1 ? p[3] : p[7];
    k0 += __shfl_xor_sync(0xffffffffu, s0, 1);
    k1 += __shfl_xor_sync(0xffffffffu, s1, 1);
    k2 += __shfl_xor_sync(0xffffffffu, s2, 1);
    k3 += __shfl_xor_sync(0xffffffffu, s3, 1);
    bool h2 = (lane & 2) != 0;
    float t0 = h2 ? k2 : k0, t1 = h2 ? k3 : k1;
    float u0 = h2 ? k0 : k2, u1 = h2 ? k1 : k3;
    t0 += __shfl_xor_sync(0xffffffffu, u0, 2);
    t1 += __shfl_xor_sync(0xffffffffu, u1, 2);
    bool h4 = (lane & 4) != 0;
    float v = h4 ? t1 : t0;
    float w = h4 ? t0 : t1;
    v += __shfl_xor_sync(0xffffffffu, w, 4);
    v += __shfl_xor_sync(0xffffffffu, v, 8);
    v += __shfl_xor_sync(0xffffffffu, v, 16);
    return v;
}
__device__ __forceinline__ int bitrev3(int l) {
    return ((l & 1) << 2) | (l & 2) | ((l >> 2) & 1);
}

__global__ void __launch_bounds__(TPB, 4)
pointer_attn_kernel(const float* __restrict__ state_t,
                    const float* __restrict__ context,
                    const int*   __restrict__ mask,
                    const float* __restrict__ Wq,
                    const float* __restrict__ Wk_mha,
                    const float* __restrict__ Wv,
                    const float* __restrict__ Wfc,
                    const float* __restrict__ Wk,
                    const int*   __restrict__ Tptr,
                    float*       __restrict__ out)
{
    __shared__ float sqkT[1024];
    __shared__ float sscr[4096];   // 4 warps x 1024 acc partials
    __shared__ float ssc[1024];
    __shared__ float sswl[32];
    __shared__ float ssq[128];
    __shared__ float ssx[128];
    __shared__ float ssxf[128];
    __shared__ float ssz[128];
    __shared__ float sstate[384];
    __shared__ float ssu[1024];
    __shared__ float sred[16];     // [0..3] warp max, [4..7] warp sum, [8..15] l per head
    __shared__ int   smask[1000];

    const int b = blockIdx.x;
    const int t = threadIdx.x;
    const int w = t >> 5, lane = t & 31;
    const float NEG_INF = __int_as_float(0xff800000u);

    // ---- prologue: masks + state ----
    for (int i = t; i < NCTX; i += TPB) smask[i] = mask[(size_t)b * NCTX + i];
    for (int i = t; i < 384; i += TPB) sstate[i] = state_t[(size_t)b * 384 + i];
    __syncthreads();

    // q[o] = state . Wq[:,o]   (thread t = o, 4-way ILP)
    {
        float a0 = 0.f, a1 = 0.f, a2 = 0.f, a3 = 0.f;
        const float* wq = Wq + t;
#pragma unroll 4
        for (int i = 0; i < 384; i += 4) {
            a0 = fmaf(sstate[i],     wq[(size_t)i * HID], a0);
            a1 = fmaf(sstate[i + 1], wq[(size_t)(i + 1) * HID], a1);
            a2 = fmaf(sstate[i + 2], wq[(size_t)(i + 2) * HID], a2);
            a3 = fmaf(sstate[i + 3], wq[(size_t)(i + 3) * HID], a3);
        }
        ssq[t] = (a0 + a1) + (a2 + a3);
    }
    __syncthreads();

    // qkT[d][h] = 0.25 * sum_j Wk_mha[d][16h+j] * q[16h+j]
    {
        int h = t & 7, d0 = t >> 3;   // d0 in 0..15
#pragma unroll
        for (int dd = 0; dd < 8; ++dd) {
            int d = d0 + dd * 16;
            float p = 0.f;
#pragma unroll
            for (int j = 0; j < 16; ++j)
                p = fmaf(Wk_mha[d * HID + h * 16 + j], ssq[h * 16 + j], p);
            sqkT[d * 8 + h] = 0.25f * p;
        }
    }
    __syncthreads();

    // hoist this lane's qk block: qkp[dd][hp] = (qk[lane*4+dd][2hp], [2hp+1])
    ull qkp[4][4];
#pragma unroll
    for (int dd = 0; dd < 4; ++dd)
#pragma unroll
        for (int hp = 0; hp < 4; ++hp)
            qkp[dd][hp] = *(const ull*)(sqkT + (lane * 4 + dd) * 8 + hp * 2);
    const int hsel = bitrev3(lane & 7);

    const float* ctxb = context + (size_t)b * NCTX * DCTX;
    const int base = w * RPW;
    const int rowlim = (NCTX - base < RPW) ? (NCTX - base) : RPW;   // 256/256/256/232

    // ---- pass 1: stream rows straight from global, no smem, no barriers ----
    ull acc[NH][2];
#pragma unroll
    for (int hh = 0; hh < NH; ++hh) { acc[hh][0] = 0ull; acc[hh][1] = 0ull; }
    float lrun = 0.f;

    for (int i0 = 0; i0 < RPW; i0 += 4) {
        float4 cv[4];
#pragma unroll
        for (int r = 0; r < 4; ++r) {
            int rr = i0 + r;
            int safe = (rr < rowlim) ? rr : 0;
            cv[r] = *(const float4*)(ctxb + (size_t)(base + safe) * DCTX + lane * 4);
        }
#pragma unroll
        for (int r = 0; r < 4; ++r) {
            int rr = i0 + r;
            // comp partials for 8 heads on this lane's 4-d chunk
            ull cc0 = f2pack(cv[r].x, cv[r].x), cc1 = f2pack(cv[r].y, cv[r].y);
            ull cc2 = f2pack(cv[r].z, cv[r].z), cc3 = f2pack(cv[r].w, cv[r].w);
            ull p01 = 0ull, p23 = 0ull, p45 = 0ull, p67 = 0ull;
            p01 = ffma2(cc0, qkp[0][0], p01); p23 = ffma2(cc0, qkp[0][1], p23);
            p45 = ffma2(cc0, qkp[0][2], p45); p67 = ffma2(cc0, qkp[0][3], p67);
            p01 = ffma2(cc1, qkp[1][0], p01); p23 = ffma2(cc1, qkp[1][1], p23);
            p45 = ffma2(cc1, qkp[1][2], p45); p67 = ffma2(cc1, qkp[1][3], p67);
            p01 = ffma2(cc2, qkp[2][0], p01); p23 = ffma2(cc2, qkp[2][1], p23);
            p45 = ffma2(cc2, qkp[2][2], p45); p67 = ffma2(cc2, qkp[2][3], p67);
            p01 = ffma2(cc3, qkp[3][0], p01); p23 = ffma2(cc3, qkp[3][1], p23);
            p45 = ffma2(cc3, qkp[3][2], p45); p67 = ffma2(cc3, qkp[3][3], p67);

            float pv[8];
            f2unpack(p01, pv[0], pv[1]); f2unpack(p23, pv[2], pv[3]);
            f2unpack(p45, pv[4], pv[5]); f2unpack(p67, pv[6], pv[7]);
            float compv = split_butterfly8(pv, lane);  // head bitrev3(lane&7), x4 replicated

            bool dead = (rr >= rowlim) || (smask[base + rr] != 0);
            float e = dead ? 0.f : __expf(compv);
            if (lane < 8) lrun += e;   // lane<8: one rep per head

            // e for head h lives (replicated) at lane bitrev3(h)
            float eh0 = __shfl_sync(0xffffffffu, e, 0);
            float eh1 = __shfl_sync(0xffffffffu, e, 4);
            float eh2 = __shfl_sync(0xffffffffu, e, 2);
            float eh3 = __shfl_sync(0xffffffffu, e, 6);
            float eh4 = __shfl_sync(0xffffffffu, e, 1);
            float eh5 = __shfl_sync(0xffffffffu, e, 5);
            float eh6 = __shfl_sync(0xffffffffu, e, 3);
            float eh7 = __shfl_sync(0xffffffffu, e, 7);

            ull c01 = f2pack(cv[r].x, cv[r].y), c23 = f2pack(cv[r].z, cv[r].w);
            ull e2;
            e2 = f2pack(eh0, eh0); acc[0][0] = ffma2(c01, e2, acc[0][0]); acc[0][1] = ffma2(c23, e2, acc[0][1]);
            e2 = f2pack(eh1, eh1); acc[1][0] = ffma2(c01, e2, acc[1][0]); acc[1][1] = ffma2(c23, e2, acc[1][1]);
            e2 = f2pack(eh2, eh2); acc[2][0] = ffma2(c01, e2, acc[2][0]); acc[2][1] = ffma2(c23, e2, acc[2][1]);
            e2 = f2pack(eh3, eh3); acc[3][0] = ffma2(c01, e2, acc[3][0]); acc[3][1] = ffma2(c23, e2, acc[3][1]);
            e2 = f2pack(eh4, eh4); acc[4][0] = ffma2(c01, e2, acc[4][0]); acc[4][1] = ffma2(c23, e2, acc[4][1]);
            e2 = f2pack(eh5, eh5); acc[5][0] = ffma2(c01, e2, acc[5][0]); acc[5][1] = ffma2(c23, e2, acc[5][1]);
            e2 = f2pack(eh6, eh6); acc[6][0] = ffma2(c01, e2, acc[6][0]); acc[6][1] = ffma2(c23, e2, acc[6][1]);
            e2 = f2pack(eh7, eh7); acc[7][0] = ffma2(c01, e2, acc[7][0]); acc[7][1] = ffma2(c23, e2, acc[7][1]);
        }
    }

    // ---- block-reduce c and l across 4 warps ----
    {
        float* scr = sscr + w * 1024;
#pragma unroll
        for (int hh = 0; hh < NH; ++hh) {
            float x0, x1, x2, x3;
            f2unpack(acc[hh][0], x0, x1);
            f2unpack(acc[hh][1], x2, x3);
            *(float4*)(scr + hh * DCTX + lane * 4) = make_float4(x0, x1, x2, x3);
        }
        if (lane < 8) sswl[w * 8 + hsel] = lrun;
    }
    __syncthreads();
#pragma unroll
    for (int jj = 0; jj < 8; ++jj) {
        int idx = t + jj * TPB;
        ssc[idx] = (sscr[idx] + sscr[1024 + idx]) + (sscr[2048 + idx] + sscr[3072 + idx]);
    }
    if (t < 8) sred[8 + t] = (sswl[t] + sswl[8 + t]) + (sswl[16 + t] + sswl[24 + t]);
    __syncthreads();

    // x[o] = (1/l_h) sum_d c[h][d] Wv[d][o]
    {
        int hh = t >> 4;
        const float* c = ssc + hh * DCTX;
        float a0 = 0.f, a1 = 0.f, a2 = 0.f, a3 = 0.f;
#pragma unroll 4
        for (int d = 0; d < DCTX; d += 4) {
            a0 = fmaf(c[d],     Wv[(size_t)d * HID + t], a0);
            a1 = fmaf(c[d + 1], Wv[(size_t)(d + 1) * HID + t], a1);
            a2 = fmaf(c[d + 2], Wv[(size_t)(d + 2) * HID + t], a2);
            a3 = fmaf(c[d + 3], Wv[(size_t)(d + 3) * HID + t], a3);
        }
        ssx[t] = ((a0 + a1) + (a2 + a3)) / sred[8 + hh];
    }
    __syncthreads();
    // xf = x @ Wfc
    {
        float a0 = 0.f, a1 = 0.f, a2 = 0.f, a3 = 0.f;
#pragma unroll 4
        for (int i = 0; i < HID; i += 4) {
            a0 = fmaf(ssx[i],     Wfc[(size_t)i * HID + t], a0);
            a1 = fmaf(ssx[i + 1], Wfc[(size_t)(i + 1) * HID + t], a1);
            a2 = fmaf(ssx[i + 2], Wfc[(size_t)(i + 2) * HID + t], a2);
            a3 = fmaf(ssx[i + 3], Wfc[(size_t)(i + 3) * HID + t], a3);
        }
        ssxf[t] = (a0 + a1) + (a2 + a3);
    }
    __syncthreads();
    // z[d] = (1/sqrt(HID)) sum_o Wk[d][o] xf[o]
    {
        const float* wk = Wk + (size_t)t * HID;
        float a0 = 0.f, a1 = 0.f, a2 = 0.f, a3 = 0.f;
#pragma unroll 4
        for (int o = 0; o < HID; o += 4) {
            a0 = fmaf(wk[o],     ssxf[o], a0);
            a1 = fmaf(wk[o + 1], ssxf[o + 1], a1);
            a2 = fmaf(wk[o + 2], ssxf[o + 2], a2);
            a3 = fmaf(wk[o + 3], ssxf[o + 3], a3);
        }
        ssz[t] = 0.08838834764831845f * ((a0 + a1) + (a2 + a3));
    }
    __syncthreads();

    // ---- pass 2: u[n] = 5*tanh(ctx[n].z), streamed from global ----
    float4 zv = *(const float4*)(ssz + lane * 4);
    ull z01 = f2pack(zv.x, zv.y), z23 = f2pack(zv.z, zv.w);

    for (int ib = 0; ib < RPW / 8; ++ib) {
        float dr[8];
#pragma unroll
        for (int r = 0; r < 8; ++r) {
            int rr = ib * 8 + r;
            int safe = (rr < rowlim) ? rr : 0;
            float4 cv = *(const float4*)(ctxb + (size_t)(base + safe) * DCTX + lane * 4);
            ull s2 = ffma2(f2pack(cv.z, cv.w), z23, 0ull);
            s2 = ffma2(f2pack(cv.x, cv.y), z01, s2);
            float a0, a1; f2unpack(s2, a0, a1);
            dr[r] = a0 + a1;
        }
        float ud = split_butterfly8(dr, lane);   // row ib*8 + bitrev3(lane&7)
        if (lane < 8) {
            int rr = ib * 8 + hsel;
            if (rr < rowlim)
                ssu[base + rr] = (smask[base + rr] != 0) ? NEG_INF : 5.f * tanhf(ud);
        }
    }
    __syncthreads();

    // ---- final masked softmax over u[0..999] ----
    float uk[8];
    float m = NEG_INF;
#pragma unroll
    for (int k = 0; k < 8; ++k) {
        int idx = t + k * TPB;
        uk[k] = (idx < NCTX) ? ssu[idx] : NEG_INF;
        m = fmaxf(m, uk[k]);
    }
    m = fmaxf(m, __shfl_xor_sync(0xffffffffu, m, 16));
    m = fmaxf(m, __shfl_xor_sync(0xffffffffu, m, 8));
    m = fmaxf(m, __shfl_xor_sync(0xffffffffu, m, 4));
    m = fmaxf(m, __shfl_xor_sync(0xffffffffu, m, 2));
    m = fmaxf(m, __shfl_xor_sync(0xffffffffu, m, 1));
    if (lane == 0) sred[w] = m;
    __syncthreads();
    float umax = fmaxf(fmaxf(sred[0], sred[1]), fmaxf(sred[2], sred[3]));

    float invT;
    {
        int iv = Tptr[0];
        float Tv = (iv >= 1 && iv <= 1000000) ? (float)iv : __int_as_float(iv);
        if (!(Tv > 0.f)) Tv = 1.f;
        invT = 1.f / Tv;
    }

    float s = 0.f;
#pragma unroll
    for (int k = 0; k < 8; ++k) {
        uk[k] = __expf((uk[k] - umax) * invT);   // -inf -> 0
        s += uk[k];
    }
    s += __shfl_xor_sync(0xffffffffu, s, 16);
    s += __shfl_xor_sync(0xffffffffu, s, 8);
    s += __shfl_xor_sync(0xffffffffu, s, 4);
    s += __shfl_xor_sync(0xffffffffu, s, 2);
    s += __shfl_xor_sync(0xffffffffu, s, 1);
    if (lane == 0) sred[4 + w] = s;
    __syncthreads();
    float inv_sum = 1.f / ((sred[4] + sred[5]) + (sred[6] + sred[7]));

#pragma unroll
    for (int k = 0; k < 8; ++k) {
        int idx = t + k * TPB;
        if (idx < NCTX) out[(size_t)b * NCTX + idx] = uk[k] * inv_sum;
    }
}

extern "C" void kernel_launch(void* const* d_in, const int* in_sizes, int n_in,
                              void* d_out, int out_size)
{
    const float* state_t = (const float*)d_in[0];
    const float* context = (const float*)d_in[1];
    const int*   mask    = (const int*)d_in[2];
    const float* Wq      = (const float*)d_in[3];
    const float* Wk_mha  = (const float*)d_in[4];
    const float* Wv      = (const float*)d_in[5];
    const float* Wfc     = (const float*)d_in[6];
    const float* Wk      = (const float*)d_in[7];
    const int*   Tptr    = (const int*)d_in[8];

    pointer_attn_kernel<<<BATCH, TPB>>>(
        state_t, context, mask, Wq, Wk_mha, Wv, Wfc, Wk, Tptr, (float*)d_out);
}